// round 1
// baseline (speedup 1.0000x reference)
#include <cuda_runtime.h>
#include <math.h>

// Problem constants
#define BB   2
#define TT   512
#define DM   1024
#define DH   4096
#define DD   4
#define VV   32000
#define ROWS (BB*TT*DD)   // 4096
#define BTN  (BB*TT)      // 1024

// Scratch (static device globals — no allocation allowed)
__device__ float  g_S [ROWS*DM];   // LN output           16 MB
__device__ float  g_G [ROWS*DH];   // GELU(MLP hidden)    64 MB
__device__ float  g_S2[ROWS*DM];   // MLP output          16 MB
__device__ float  g_beta[ROWS];
__device__ double g_acc[4];        // nll_sum, cnt, bce_sum, src_cnt

// ---------------------------------------------------------------------------
__global__ void zero_acc_kernel() {
    if (threadIdx.x < 4) g_acc[threadIdx.x] = 0.0;
}

// ---------------------------------------------------------------------------
// S = LayerNorm(H + emb[ids] + depth_emb[d]) * g + b   (one block per row)
__global__ void s_kernel(const float* __restrict__ H, const int* __restrict__ ids,
                         const float* __restrict__ emb, const float* __restrict__ demb,
                         const float* __restrict__ lng, const float* __restrict__ lnb)
{
    int r   = blockIdx.x;          // 0..4095
    int bt  = r >> 2;
    int d   = r & 3;
    int tid = threadIdx.x;         // 256 threads, 4 elems each

    const float* hrow = H    + (size_t)bt * DM;
    const float* erow = emb  + (size_t)ids[bt] * DM;
    const float* drow = demb + (size_t)d * DM;

    float x[4];
    float s = 0.f;
#pragma unroll
    for (int j = 0; j < 4; j++) {
        int i = j * 256 + tid;
        x[j] = hrow[i] + erow[i] + drow[i];
        s += x[j];
    }
    __shared__ float red[256];
    red[tid] = s; __syncthreads();
    for (int o = 128; o > 0; o >>= 1) { if (tid < o) red[tid] += red[tid + o]; __syncthreads(); }
    float mu = red[0] * (1.0f / DM);
    __syncthreads();

    float v = 0.f;
#pragma unroll
    for (int j = 0; j < 4; j++) { float dx = x[j] - mu; v += dx * dx; }
    red[tid] = v; __syncthreads();
    for (int o = 128; o > 0; o >>= 1) { if (tid < o) red[tid] += red[tid + o]; __syncthreads(); }
    float inv = rsqrtf(red[0] * (1.0f / DM) + 1e-5f);

#pragma unroll
    for (int j = 0; j < 4; j++) {
        int i = j * 256 + tid;
        g_S[(size_t)r * DM + i] = (x[j] - mu) * inv * lng[i] + lnb[i];
    }
}

// ---------------------------------------------------------------------------
// 128x128x8 register-blocked SGEMM, 256 threads, 8x8 per-thread microtile.
// MODE 0: C = gelu(A@B + bias)      (MLP up)
// MODE 1: C = A@B + bias            (MLP down)
// MODE 2: C = mask ? A@B + bias : 0 (logits)
template<int MODE>
__global__ void __launch_bounds__(256, 2)
gemm_kernel(const float* __restrict__ A, const float* __restrict__ Bm,
            const float* __restrict__ bias, float* __restrict__ C,
            int N, int K, const int* __restrict__ mask)
{
    __shared__ float As[8][128];
    __shared__ float Bs[8][128];

    int tid = threadIdx.x;
    int tm  = tid >> 4;          // 0..15
    int tn  = tid & 15;          // 0..15
    int rowBase = blockIdx.y * 128;
    int colBase = blockIdx.x * 128;

    int arow = tid >> 1;         // 0..127
    int ak   = (tid & 1) * 4;    // 0 or 4
    int bk   = tid >> 5;         // 0..7
    int bn   = (tid & 31) * 4;   // 0..124

    const float* Aptr = A  + (size_t)(rowBase + arow) * K + ak;
    const float* Bptr = Bm + (size_t)bk * N + colBase + bn;

    float acc[8][8];
#pragma unroll
    for (int i = 0; i < 8; i++)
#pragma unroll
        for (int j = 0; j < 8; j++) acc[i][j] = 0.f;

    for (int k0 = 0; k0 < K; k0 += 8) {
        float4 a4 = *(const float4*)(Aptr + k0);
        float4 b4 = *(const float4*)(Bptr + (size_t)k0 * N);
        __syncthreads();
        As[ak + 0][arow] = a4.x;
        As[ak + 1][arow] = a4.y;
        As[ak + 2][arow] = a4.z;
        As[ak + 3][arow] = a4.w;
        *(float4*)&Bs[bk][bn] = b4;
        __syncthreads();
#pragma unroll
        for (int k = 0; k < 8; k++) {
            float a[8], b[8];
#pragma unroll
            for (int i = 0; i < 8; i++) a[i] = As[k][tm * 8 + i];
#pragma unroll
            for (int j = 0; j < 8; j++) b[j] = Bs[k][tn * 8 + j];
#pragma unroll
            for (int i = 0; i < 8; i++)
#pragma unroll
                for (int j = 0; j < 8; j++) acc[i][j] += a[i] * b[j];
        }
    }

#pragma unroll
    for (int i = 0; i < 8; i++) {
        int r = rowBase + tm * 8 + i;
        float mval = 1.f;
        if (MODE == 2) mval = (mask[r >> 2] != 0) ? 1.f : 0.f;
#pragma unroll
        for (int j = 0; j < 8; j++) {
            int c = colBase + tn * 8 + j;
            float v = acc[i][j] + bias[c];
            if (MODE == 0) v = 0.5f * v * (1.0f + erff(v * 0.70710678118654752f));
            if (MODE == 2) v *= mval;
            C[(size_t)r * N + c] = v;
        }
    }
}

// ---------------------------------------------------------------------------
// beta = S2 @ Wb + bb (masked) ; k = dynamic branch width (written as float)
__global__ void beta_kernel(const float* __restrict__ Wb, const float* __restrict__ bbq,
                            const int* __restrict__ mask,
                            float* __restrict__ obeta, float* __restrict__ ok)
{
    int r   = blockIdx.x;
    int tid = threadIdx.x;
    const float* row = g_S2 + (size_t)r * DM;
    float s = 0.f;
    for (int i = tid; i < DM; i += 256) s += row[i] * Wb[i];
    __shared__ float red[256];
    red[tid] = s; __syncthreads();
    for (int o = 128; o > 0; o >>= 1) { if (tid < o) red[tid] += red[tid + o]; __syncthreads(); }
    if (tid == 0) {
        float be = red[0] + bbq[0];
        int   m  = mask[r >> 2];
        float bm = m ? be : 0.f;
        obeta[r]  = bm;
        g_beta[r] = bm;
        float sig = 1.f / (1.f + expf(-bm));
        int k = (int)ceilf(sig * 8.f);
        k = max(1, min(8, k));
        if (sig < 0.25f) k = 0;
        if (!m)          k = 0;
        ok[r] = (float)k;
    }
}

// ---------------------------------------------------------------------------
// Token CE: nll over valid (b,t,d) rows of q (one block per row)
__global__ void nll_kernel(const float* __restrict__ q, const int* __restrict__ mask,
                           const int* __restrict__ labels)
{
    int r  = blockIdx.x;
    int d  = r & 3;
    int bt = r >> 2;
    int t  = bt % TT;
    int b  = bt / TT;
    int td = t + d + 1;
    bool valid = (td < TT) && (mask[bt] != 0) && (mask[b * TT + td] != 0);
    if (!valid) return;
    int tgt = labels[b * TT + td];

    const float* row = q + (size_t)r * VV;
    int tid = threadIdx.x;
    __shared__ float red[256];

    float mx = -INFINITY;
    for (int i = tid; i < VV; i += 256) mx = fmaxf(mx, row[i]);
    red[tid] = mx; __syncthreads();
    for (int o = 128; o > 0; o >>= 1) { if (tid < o) red[tid] = fmaxf(red[tid], red[tid + o]); __syncthreads(); }
    mx = red[0]; __syncthreads();

    float se = 0.f;
    for (int i = tid; i < VV; i += 256) se += expf(row[i] - mx);
    red[tid] = se; __syncthreads();
    for (int o = 128; o > 0; o >>= 1) { if (tid < o) red[tid] += red[tid + o]; __syncthreads(); }

    if (tid == 0) {
        float nll = logf(red[0]) + mx - row[tgt];
        atomicAdd(&g_acc[0], (double)nll);
        atomicAdd(&g_acc[1], 1.0);
    }
}

// ---------------------------------------------------------------------------
// BCE-with-logits over source positions (one thread per (b,t))
__global__ void bce_kernel(const int* __restrict__ mask)
{
    int idx = blockIdx.x * 256 + threadIdx.x;   // 0..1023
    if (idx >= BTN) return;
    int t = idx % TT;
    int b = idx / TT;
    bool m0 = (mask[idx] != 0);
    float bsum = 0.f;
    bool anyv = false;
#pragma unroll
    for (int d = 0; d < 4; d++) {
        int td = t + d + 1;
        bool valid = m0 && (td < TT) && (mask[b * TT + td] != 0);
        float be  = g_beta[idx * 4 + d];
        float bce = fmaxf(be, 0.f) + log1pf(expf(-fabsf(be))) - (valid ? be : 0.f);
        bsum += bce;
        anyv |= valid;
    }
    if (anyv) {
        atomicAdd(&g_acc[2], (double)bsum);
        atomicAdd(&g_acc[3], 1.0);
    }
}

// ---------------------------------------------------------------------------
__global__ void fin_kernel(float* __restrict__ oloss)
{
    double cnt = g_acc[1];
    double Lq  = (cnt > 0.0) ? g_acc[0] / cnt : 0.0;
    double den = g_acc[3]; if (den < 1.0) den = 1.0;
    double Lb  = g_acc[2] / den;
    oloss[0] = (float)(Lq + Lb);
}

// ---------------------------------------------------------------------------
extern "C" void kernel_launch(void* const* d_in, const int* in_sizes, int n_in,
                              void* d_out, int out_size)
{
    const float* H      = (const float*)d_in[0];
    const int*   ids    = (const int*)  d_in[1];
    const int*   mask   = (const int*)  d_in[2];
    const int*   labels = (const int*)  d_in[3];
    const float* emb    = (const float*)d_in[4];
    const float* demb   = (const float*)d_in[5];
    const float* ln_g   = (const float*)d_in[6];
    const float* ln_b   = (const float*)d_in[7];
    const float* W1     = (const float*)d_in[8];
    const float* b1     = (const float*)d_in[9];
    const float* W2     = (const float*)d_in[10];
    const float* b2     = (const float*)d_in[11];
    const float* Wq     = (const float*)d_in[12];
    const float* bq     = (const float*)d_in[13];
    const float* Wb     = (const float*)d_in[14];
    const float* bb     = (const float*)d_in[15];

    float* out   = (float*)d_out;
    float* q     = out;                              // (B,T,DD,V)
    float* obeta = out + (size_t)ROWS * VV;          // (B,T,DD)
    float* ok    = obeta + ROWS;                     // (B,T,DD)
    float* oloss = ok + ROWS;                        // scalar

    // Scratch symbol addresses (query only — no allocation)
    void *pS, *pG, *pS2;
    cudaGetSymbolAddress(&pS,  g_S);
    cudaGetSymbolAddress(&pG,  g_G);
    cudaGetSymbolAddress(&pS2, g_S2);

    zero_acc_kernel<<<1, 32>>>();

    s_kernel<<<ROWS, 256>>>(H, ids, emb, demb, ln_g, ln_b);

    // G = gelu(S @ W1 + b1)    : M=4096, N=4096, K=1024
    gemm_kernel<0><<<dim3(DH / 128, ROWS / 128), 256>>>(
        (const float*)pS, W1, b1, (float*)pG, DH, DM, nullptr);

    // S2 = G @ W2 + b2         : M=4096, N=1024, K=4096
    gemm_kernel<1><<<dim3(DM / 128, ROWS / 128), 256>>>(
        (const float*)pG, W2, b2, (float*)pS2, DM, DH, nullptr);

    // q = mask ? S2 @ Wq + bq : 0   : M=4096, N=32000, K=1024
    gemm_kernel<2><<<dim3(VV / 128, ROWS / 128), 256>>>(
        (const float*)pS2, Wq, bq, q, VV, DM, mask);

    beta_kernel<<<ROWS, 256>>>(Wb, bb, mask, obeta, ok);

    nll_kernel<<<ROWS, 256>>>(q, mask, labels);
    bce_kernel<<<(BTN + 255) / 256, 256>>>(mask);
    fin_kernel<<<1, 1>>>(oloss);

    (void)in_sizes; (void)n_in; (void)out_size;
}

// round 3
// speedup vs baseline: 2.2455x; 2.2455x over previous
#include <cuda_runtime.h>
#include <math.h>
#include <stdint.h>

// Problem constants
#define BB   2
#define TT   512
#define DM   1024
#define DH   4096
#define DD   4
#define VV   32000
#define ROWS (BB*TT*DD)   // 4096
#define BTN  (BB*TT)      // 1024

// Scratch (static device globals — no allocation allowed)
__device__ float  g_S  [ROWS*DM];     // LN output
__device__ float  g_G  [ROWS*DH];     // GELU(MLP hidden)
__device__ float  g_S2 [ROWS*DM];     // MLP output (fp32 exact)
__device__ float  g_S2r[ROWS*DM];     // tf32-rounded S2
__device__ float  g_Wt [VV*DM];       // transposed+rounded Wq
__device__ float  g_beta[ROWS];
__device__ double g_acc[4];

// ============================================================================
__device__ __forceinline__ uint32_t smem_u32(const void* p) {
    uint32_t a;
    asm("{ .reg .u64 t; cvta.to.shared.u64 t, %1; cvt.u32.u64 %0, t; }"
        : "=r"(a) : "l"(p));
    return a;
}
__device__ __forceinline__ float rna_tf32(float v) {
    uint32_t r;
    asm("cvt.rna.tf32.f32 %0, %1;" : "=r"(r) : "f"(v));
    return __uint_as_float(r);
}
__device__ __forceinline__ void cp8(uint32_t s, const void* g) {
    asm volatile("cp.async.ca.shared.global [%0], [%1], 8;" :: "r"(s), "l"(g));
}
#define CP_COMMIT() asm volatile("cp.async.commit_group;" ::: "memory")
#define CP_WAIT0()  asm volatile("cp.async.wait_group 0;" ::: "memory")

__device__ __forceinline__ void mma_tf32_16x8x8(float* d, const uint32_t* a,
                                                const uint32_t* b) {
    asm volatile(
        "mma.sync.aligned.m16n8k8.row.col.f32.tf32.tf32.f32 "
        "{%0,%1,%2,%3}, {%4,%5,%6,%7}, {%8,%9}, {%0,%1,%2,%3};"
        : "+f"(d[0]), "+f"(d[1]), "+f"(d[2]), "+f"(d[3])
        : "r"(a[0]), "r"(a[1]), "r"(a[2]), "r"(a[3]), "r"(b[0]), "r"(b[1]));
}

// ============================================================================
__global__ void zero_acc_kernel() {
    if (threadIdx.x < 4) g_acc[threadIdx.x] = 0.0;
}

// ---------------------------------------------------------------------------
// S = LayerNorm(H + emb[ids] + depth_emb[d]) * g + b   (one block per row)
__global__ void s_kernel(const float* __restrict__ H, const int* __restrict__ ids,
                         const float* __restrict__ emb, const float* __restrict__ demb,
                         const float* __restrict__ lng, const float* __restrict__ lnb)
{
    int r   = blockIdx.x;
    int bt  = r >> 2;
    int d   = r & 3;
    int tid = threadIdx.x;

    const float* hrow = H    + (size_t)bt * DM;
    const float* erow = emb  + (size_t)ids[bt] * DM;
    const float* drow = demb + (size_t)d * DM;

    float x[4];
    float s = 0.f;
#pragma unroll
    for (int j = 0; j < 4; j++) {
        int i = j * 256 + tid;
        x[j] = hrow[i] + erow[i] + drow[i];
        s += x[j];
    }
    __shared__ float red[256];
    red[tid] = s; __syncthreads();
    for (int o = 128; o > 0; o >>= 1) { if (tid < o) red[tid] += red[tid + o]; __syncthreads(); }
    float mu = red[0] * (1.0f / DM);
    __syncthreads();

    float v = 0.f;
#pragma unroll
    for (int j = 0; j < 4; j++) { float dx = x[j] - mu; v += dx * dx; }
    red[tid] = v; __syncthreads();
    for (int o = 128; o > 0; o >>= 1) { if (tid < o) red[tid] += red[tid + o]; __syncthreads(); }
    float inv = rsqrtf(red[0] * (1.0f / DM) + 1e-5f);

#pragma unroll
    for (int j = 0; j < 4; j++) {
        int i = j * 256 + tid;
        g_S[(size_t)r * DM + i] = (x[j] - mu) * inv * lng[i] + lnb[i];
    }
}

// ---------------------------------------------------------------------------
// 128x128x8 register-blocked SGEMM (MLP path, fp32 exact)
// MODE 0: C = gelu(A@B + bias)   MODE 1: C = A@B + bias
template<int MODE>
__global__ void __launch_bounds__(256, 2)
gemm_kernel(const float* __restrict__ A, const float* __restrict__ Bm,
            const float* __restrict__ bias, float* __restrict__ C,
            int N, int K)
{
    __shared__ float As[8][128];
    __shared__ float Bs[8][128];

    int tid = threadIdx.x;
    int tm  = tid >> 4;
    int tn  = tid & 15;
    int rowBase = blockIdx.y * 128;
    int colBase = blockIdx.x * 128;

    int arow = tid >> 1;
    int ak   = (tid & 1) * 4;
    int bk   = tid >> 5;
    int bn   = (tid & 31) * 4;

    const float* Aptr = A  + (size_t)(rowBase + arow) * K + ak;
    const float* Bptr = Bm + (size_t)bk * N + colBase + bn;

    float acc[8][8];
#pragma unroll
    for (int i = 0; i < 8; i++)
#pragma unroll
        for (int j = 0; j < 8; j++) acc[i][j] = 0.f;

    for (int k0 = 0; k0 < K; k0 += 8) {
        float4 a4 = *(const float4*)(Aptr + k0);
        float4 b4 = *(const float4*)(Bptr + (size_t)k0 * N);
        __syncthreads();
        As[ak + 0][arow] = a4.x;
        As[ak + 1][arow] = a4.y;
        As[ak + 2][arow] = a4.z;
        As[ak + 3][arow] = a4.w;
        *(float4*)&Bs[bk][bn] = b4;
        __syncthreads();
#pragma unroll
        for (int k = 0; k < 8; k++) {
            float a[8], b[8];
#pragma unroll
            for (int i = 0; i < 8; i++) a[i] = As[k][tm * 8 + i];
#pragma unroll
            for (int j = 0; j < 8; j++) b[j] = Bs[k][tn * 8 + j];
#pragma unroll
            for (int i = 0; i < 8; i++)
#pragma unroll
                for (int j = 0; j < 8; j++) acc[i][j] += a[i] * b[j];
        }
    }

#pragma unroll
    for (int i = 0; i < 8; i++) {
        int r = rowBase + tm * 8 + i;
#pragma unroll
        for (int j = 0; j < 8; j++) {
            int c = colBase + tn * 8 + j;
            float v = acc[i][j] + bias[c];
            if (MODE == 0) v = 0.5f * v * (1.0f + erff(v * 0.70710678118654752f));
            C[(size_t)r * N + c] = v;
        }
    }
}

// ---------------------------------------------------------------------------
// Round S2 -> tf32 copy
__global__ void round_s2_kernel() {
    int i = blockIdx.x * 256 + threadIdx.x;
    g_S2r[i] = rna_tf32(g_S2[i]);
}

// Transpose + round Wq [DM][VV] -> Wt [VV][DM]
__global__ void transpose_round_kernel(const float* __restrict__ W) {
    __shared__ float tile[32][33];
    int bx = blockIdx.x;
    int by = blockIdx.y;
    int x  = threadIdx.x;
    int y0 = threadIdx.y;
#pragma unroll
    for (int yy = 0; yy < 32; yy += 8) {
        float v = W[(size_t)(by * 32 + y0 + yy) * VV + bx * 32 + x];
        tile[y0 + yy][x] = rna_tf32(v);
    }
    __syncthreads();
#pragma unroll
    for (int yy = 0; yy < 32; yy += 8) {
        g_Wt[(size_t)(bx * 32 + y0 + yy) * DM + by * 32 + x] = tile[x][y0 + yy];
    }
}

// ---------------------------------------------------------------------------
// tf32 mma.sync logits GEMM: q[4096,32000] = mask * (S2r @ Wt^T + bq)
// CTA 128x128, K-chunk 32, 2-stage cp.async, 8 warps (4x2), warp tile 32x64.
#define KCH    32
#define NITER  (DM / KCH)     // 32
#define LSTR   36             // smem row stride (floats), conflict-free frags
#define TILE_F (128 * LSTR)   // 4608 floats per tile
#define STG_F  (2 * TILE_F)   // A+B per stage

__global__ void __launch_bounds__(256, 1)
logits_kernel(const float* __restrict__ Ar, const float* __restrict__ Bt,
              const float* __restrict__ bq, const int* __restrict__ mask,
              float* __restrict__ q)
{
    extern __shared__ float smem[];
    const uint32_t su = smem_u32(smem);
    const int tid     = threadIdx.x;
    const int rowBase = blockIdx.x * 128;   // M-fast for L2 B reuse
    const int colBase = blockIdx.y * 128;

    const int lane = tid & 31, wid = tid >> 5;
    const int wr = wid >> 1, wc = wid & 1;          // 4x2 warp grid
    const int g  = lane >> 2, tig = lane & 3;

    float acc[2][8][4];
#pragma unroll
    for (int mt = 0; mt < 2; mt++)
#pragma unroll
        for (int nt = 0; nt < 8; nt++)
#pragma unroll
            for (int k = 0; k < 4; k++) acc[mt][nt][k] = 0.f;

    const float* agbase = Ar + (size_t)rowBase * DM;
    const float* bgbase = Bt + (size_t)colBase * DM;

    auto load_stage = [&](int s, int c) {
        uint32_t abase = su + (s * STG_F) * 4;
        uint32_t bbase = su + (s * STG_F + TILE_F) * 4;
        const float* ag = agbase + c * KCH;
        const float* bg = bgbase + c * KCH;
#pragma unroll
        for (int j = 0; j < 8; j++) {
            int idx = tid + 256 * j;           // 0..2047
            int row = idx >> 4, seg = idx & 15;
            cp8(abase + (row * LSTR + seg * 2) * 4, ag + (size_t)row * DM + seg * 2);
        }
#pragma unroll
        for (int j = 0; j < 8; j++) {
            int idx = tid + 256 * j;
            int row = idx >> 4, seg = idx & 15;
            cp8(bbase + (row * LSTR + seg * 2) * 4, bg + (size_t)row * DM + seg * 2);
        }
    };

    load_stage(0, 0);
    CP_COMMIT();

    for (int it = 0; it < NITER; it++) {
        int s = it & 1;
        CP_WAIT0();
        __syncthreads();
        if (it + 1 < NITER) { load_stage(1 - s, it + 1); CP_COMMIT(); }

        const float* As = smem + s * STG_F;
        const float* Bs = smem + s * STG_F + TILE_F;

#pragma unroll
        for (int k8 = 0; k8 < 4; k8++) {
            int kb = k8 * 8;
            uint32_t a[2][4];
#pragma unroll
            for (int mt = 0; mt < 2; mt++) {
                int m0 = wr * 32 + mt * 16;
                a[mt][0] = __float_as_uint(As[(m0 + g    ) * LSTR + kb + tig    ]);
                a[mt][1] = __float_as_uint(As[(m0 + g + 8) * LSTR + kb + tig    ]);
                a[mt][2] = __float_as_uint(As[(m0 + g    ) * LSTR + kb + tig + 4]);
                a[mt][3] = __float_as_uint(As[(m0 + g + 8) * LSTR + kb + tig + 4]);
            }
            uint32_t b[8][2];
#pragma unroll
            for (int nt = 0; nt < 8; nt++) {
                int n0 = wc * 64 + nt * 8;
                b[nt][0] = __float_as_uint(Bs[(n0 + g) * LSTR + kb + tig    ]);
                b[nt][1] = __float_as_uint(Bs[(n0 + g) * LSTR + kb + tig + 4]);
            }
#pragma unroll
            for (int mt = 0; mt < 2; mt++)
#pragma unroll
                for (int nt = 0; nt < 8; nt++)
                    mma_tf32_16x8x8(acc[mt][nt], a[mt], b[nt]);
        }
        __syncthreads();
    }

    // Epilogue: bias + mask, direct float2 stores
#pragma unroll
    for (int mt = 0; mt < 2; mt++) {
        int rb = rowBase + wr * 32 + mt * 16;
        int r0 = rb + g, r1 = rb + g + 8;
        float m0 = (mask[r0 >> 2] != 0) ? 1.f : 0.f;
        float m1 = (mask[r1 >> 2] != 0) ? 1.f : 0.f;
#pragma unroll
        for (int nt = 0; nt < 8; nt++) {
            int c = colBase + wc * 64 + nt * 8 + tig * 2;
            float bq0 = bq[c], bq1 = bq[c + 1];
            float2 v0 = make_float2((acc[mt][nt][0] + bq0) * m0,
                                    (acc[mt][nt][1] + bq1) * m0);
            float2 v1 = make_float2((acc[mt][nt][2] + bq0) * m1,
                                    (acc[mt][nt][3] + bq1) * m1);
            *(float2*)&q[(size_t)r0 * VV + c] = v0;
            *(float2*)&q[(size_t)r1 * VV + c] = v1;
        }
    }
}

// ---------------------------------------------------------------------------
// beta = S2 @ Wb + bb (masked) ; k = dynamic branch width
__global__ void beta_kernel(const float* __restrict__ Wb, const float* __restrict__ bbq,
                            const int* __restrict__ mask,
                            float* __restrict__ obeta, float* __restrict__ ok)
{
    int r   = blockIdx.x;
    int tid = threadIdx.x;
    const float* row = g_S2 + (size_t)r * DM;
    float s = 0.f;
    for (int i = tid; i < DM; i += 256) s += row[i] * Wb[i];
    __shared__ float red[256];
    red[tid] = s; __syncthreads();
    for (int o = 128; o > 0; o >>= 1) { if (tid < o) red[tid] += red[tid + o]; __syncthreads(); }
    if (tid == 0) {
        float be = red[0] + bbq[0];
        int   m  = mask[r >> 2];
        float bm = m ? be : 0.f;
        obeta[r]  = bm;
        g_beta[r] = bm;
        float sig = 1.f / (1.f + expf(-bm));
        int k = (int)ceilf(sig * 8.f);
        k = max(1, min(8, k));
        if (sig < 0.25f) k = 0;
        if (!m)          k = 0;
        ok[r] = (float)k;
    }
}

// ---------------------------------------------------------------------------
__global__ void nll_kernel(const float* __restrict__ q, const int* __restrict__ mask,
                           const int* __restrict__ labels)
{
    int r  = blockIdx.x;
    int d  = r & 3;
    int bt = r >> 2;
    int t  = bt % TT;
    int b  = bt / TT;
    int td = t + d + 1;
    bool valid = (td < TT) && (mask[bt] != 0) && (mask[b * TT + td] != 0);
    if (!valid) return;
    int tgt = labels[b * TT + td];

    const float* row = q + (size_t)r * VV;
    int tid = threadIdx.x;
    __shared__ float red[256];

    float mx = -INFINITY;
    for (int i = tid; i < VV; i += 256) mx = fmaxf(mx, row[i]);
    red[tid] = mx; __syncthreads();
    for (int o = 128; o > 0; o >>= 1) { if (tid < o) red[tid] = fmaxf(red[tid], red[tid + o]); __syncthreads(); }
    mx = red[0]; __syncthreads();

    float se = 0.f;
    for (int i = tid; i < VV; i += 256) se += expf(row[i] - mx);
    red[tid] = se; __syncthreads();
    for (int o = 128; o > 0; o >>= 1) { if (tid < o) red[tid] += red[tid + o]; __syncthreads(); }

    if (tid == 0) {
        float nll = logf(red[0]) + mx - row[tgt];
        atomicAdd(&g_acc[0], (double)nll);
        atomicAdd(&g_acc[1], 1.0);
    }
}

// ---------------------------------------------------------------------------
__global__ void bce_kernel(const int* __restrict__ mask)
{
    int idx = blockIdx.x * 256 + threadIdx.x;
    if (idx >= BTN) return;
    int t = idx % TT;
    int b = idx / TT;
    bool m0 = (mask[idx] != 0);
    float bsum = 0.f;
    bool anyv = false;
#pragma unroll
    for (int d = 0; d < 4; d++) {
        int td = t + d + 1;
        bool valid = m0 && (td < TT) && (mask[b * TT + td] != 0);
        float be  = g_beta[idx * 4 + d];
        float bce = fmaxf(be, 0.f) + log1pf(expf(-fabsf(be))) - (valid ? be : 0.f);
        bsum += bce;
        anyv |= valid;
    }
    if (anyv) {
        atomicAdd(&g_acc[2], (double)bsum);
        atomicAdd(&g_acc[3], 1.0);
    }
}

// ---------------------------------------------------------------------------
__global__ void fin_kernel(float* __restrict__ oloss)
{
    double cnt = g_acc[1];
    double Lq  = (cnt > 0.0) ? g_acc[0] / cnt : 0.0;
    double den = g_acc[3]; if (den < 1.0) den = 1.0;
    double Lb  = g_acc[2] / den;
    oloss[0] = (float)(Lq + Lb);
}

// ---------------------------------------------------------------------------
extern "C" void kernel_launch(void* const* d_in, const int* in_sizes, int n_in,
                              void* d_out, int out_size)
{
    const float* H      = (const float*)d_in[0];
    const int*   ids    = (const int*)  d_in[1];
    const int*   mask   = (const int*)  d_in[2];
    const int*   labels = (const int*)  d_in[3];
    const float* emb    = (const float*)d_in[4];
    const float* demb   = (const float*)d_in[5];
    const float* ln_g   = (const float*)d_in[6];
    const float* ln_b   = (const float*)d_in[7];
    const float* W1     = (const float*)d_in[8];
    const float* b1     = (const float*)d_in[9];
    const float* W2     = (const float*)d_in[10];
    const float* b2     = (const float*)d_in[11];
    const float* Wq     = (const float*)d_in[12];
    const float* bq     = (const float*)d_in[13];
    const float* Wb     = (const float*)d_in[14];
    const float* bb     = (const float*)d_in[15];

    float* out   = (float*)d_out;
    float* q     = out;
    float* obeta = out + (size_t)ROWS * VV;
    float* ok    = obeta + ROWS;
    float* oloss = ok + ROWS;

    void *pS, *pG, *pS2, *pS2r, *pWt;
    cudaGetSymbolAddress(&pS,   g_S);
    cudaGetSymbolAddress(&pG,   g_G);
    cudaGetSymbolAddress(&pS2,  g_S2);
    cudaGetSymbolAddress(&pS2r, g_S2r);
    cudaGetSymbolAddress(&pWt,  g_Wt);

    const int smem_bytes = 2 * STG_F * 4;   // 73728
    cudaFuncSetAttribute(logits_kernel,
                         cudaFuncAttributeMaxDynamicSharedMemorySize, smem_bytes);

    zero_acc_kernel<<<1, 32>>>();

    transpose_round_kernel<<<dim3(VV / 32, DM / 32), dim3(32, 8)>>>(Wq);

    s_kernel<<<ROWS, 256>>>(H, ids, emb, demb, ln_g, ln_b);

    gemm_kernel<0><<<dim3(DH / 128, ROWS / 128), 256>>>(
        (const float*)pS, W1, b1, (float*)pG, DH, DM);

    gemm_kernel<1><<<dim3(DM / 128, ROWS / 128), 256>>>(
        (const float*)pG, W2, b2, (float*)pS2, DM, DH);

    round_s2_kernel<<<ROWS * DM / 256, 256>>>();

    logits_kernel<<<dim3(ROWS / 128, VV / 128), 256, smem_bytes>>>(
        (const float*)pS2r, (const float*)pWt, bq, mask, q);

    beta_kernel<<<ROWS, 256>>>(Wb, bb, mask, obeta, ok);

    nll_kernel<<<ROWS, 256>>>(q, mask, labels);
    bce_kernel<<<(BTN + 255) / 256, 256>>>(mask);
    fin_kernel<<<1, 1>>>(oloss);

    (void)in_sizes; (void)n_in; (void)out_size;
}

// round 4
// speedup vs baseline: 2.6651x; 1.1869x over previous
#include <cuda_runtime.h>
#include <math.h>
#include <stdint.h>

// Problem constants
#define BB   2
#define TT   512
#define DM   1024
#define DH   4096
#define DD   4
#define VV   32000
#define ROWS (BB*TT*DD)   // 4096
#define BTN  (BB*TT)      // 1024

// Scratch (static device globals — no allocation allowed)
__device__ float  g_Shi [ROWS*DM];
__device__ float  g_Slo [ROWS*DM];
__device__ float  g_Ghi [ROWS*DH];
__device__ float  g_Glo [ROWS*DH];
__device__ float  g_W1thi[DH*DM];
__device__ float  g_W1tlo[DH*DM];
__device__ float  g_W2thi[DM*DH];
__device__ float  g_W2tlo[DM*DH];
__device__ float  g_S2 [ROWS*DM];     // exact fp32 S2 (for beta)
__device__ float  g_S2r[ROWS*DM];     // tf32-rounded S2 (for logits)
__device__ float  g_Wt [VV*DM];       // transposed+rounded Wq
__device__ float  g_beta[ROWS];
__device__ double g_acc[4];

// ============================================================================
__device__ __forceinline__ uint32_t smem_u32(const void* p) {
    uint32_t a;
    asm("{ .reg .u64 t; cvta.to.shared.u64 t, %1; cvt.u32.u64 %0, t; }"
        : "=r"(a) : "l"(p));
    return a;
}
__device__ __forceinline__ float rna_tf32(float v) {
    uint32_t r;
    asm("cvt.rna.tf32.f32 %0, %1;" : "=r"(r) : "f"(v));
    return __uint_as_float(r);
}
__device__ __forceinline__ void cp8(uint32_t s, const void* g) {
    asm volatile("cp.async.ca.shared.global [%0], [%1], 8;" :: "r"(s), "l"(g));
}
__device__ __forceinline__ void cp16(uint32_t s, const void* g) {
    asm volatile("cp.async.cg.shared.global [%0], [%1], 16;" :: "r"(s), "l"(g));
}
#define CP_COMMIT() asm volatile("cp.async.commit_group;" ::: "memory")
#define CP_WAIT0()  asm volatile("cp.async.wait_group 0;" ::: "memory")

__device__ __forceinline__ void mma_tf32_16x8x8(float* d, const uint32_t* a,
                                                const uint32_t* b) {
    asm volatile(
        "mma.sync.aligned.m16n8k8.row.col.f32.tf32.tf32.f32 "
        "{%0,%1,%2,%3}, {%4,%5,%6,%7}, {%8,%9}, {%0,%1,%2,%3};"
        : "+f"(d[0]), "+f"(d[1]), "+f"(d[2]), "+f"(d[3])
        : "r"(a[0]), "r"(a[1]), "r"(a[2]), "r"(a[3]), "r"(b[0]), "r"(b[1]));
}

// ============================================================================
__global__ void zero_acc_kernel() {
    if (threadIdx.x < 4) g_acc[threadIdx.x] = 0.0;
}

// ---------------------------------------------------------------------------
// S = LayerNorm(H + emb[ids] + depth_emb[d]) * g + b  -> hi/lo tf32 split
__global__ void s_kernel(const float* __restrict__ H, const int* __restrict__ ids,
                         const float* __restrict__ emb, const float* __restrict__ demb,
                         const float* __restrict__ lng, const float* __restrict__ lnb)
{
    int r   = blockIdx.x;
    int bt  = r >> 2;
    int d   = r & 3;
    int tid = threadIdx.x;

    const float* hrow = H    + (size_t)bt * DM;
    const float* erow = emb  + (size_t)ids[bt] * DM;
    const float* drow = demb + (size_t)d * DM;

    float x[4];
    float s = 0.f;
#pragma unroll
    for (int j = 0; j < 4; j++) {
        int i = j * 256 + tid;
        x[j] = hrow[i] + erow[i] + drow[i];
        s += x[j];
    }
    __shared__ float red[256];
    red[tid] = s; __syncthreads();
    for (int o = 128; o > 0; o >>= 1) { if (tid < o) red[tid] += red[tid + o]; __syncthreads(); }
    float mu = red[0] * (1.0f / DM);
    __syncthreads();

    float v = 0.f;
#pragma unroll
    for (int j = 0; j < 4; j++) { float dx = x[j] - mu; v += dx * dx; }
    red[tid] = v; __syncthreads();
    for (int o = 128; o > 0; o >>= 1) { if (tid < o) red[tid] += red[tid + o]; __syncthreads(); }
    float inv = rsqrtf(red[0] * (1.0f / DM) + 1e-5f);

#pragma unroll
    for (int j = 0; j < 4; j++) {
        int i = j * 256 + tid;
        float val = (x[j] - mu) * inv * lng[i] + lnb[i];
        float hi  = rna_tf32(val);
        g_Shi[(size_t)r * DM + i] = hi;
        g_Slo[(size_t)r * DM + i] = rna_tf32(val - hi);
    }
}

// ---------------------------------------------------------------------------
// Transpose + tf32-split: src[R,C] row-major -> dst_hi/lo[C,R]
__global__ void transpose_split_kernel(const float* __restrict__ W,
                                       float* __restrict__ Dhi, float* __restrict__ Dlo,
                                       int R, int C)
{
    __shared__ float tile[32][33];
    int bx = blockIdx.x;   // C/32
    int by = blockIdx.y;   // R/32
    int x  = threadIdx.x;
    int y0 = threadIdx.y;
#pragma unroll
    for (int yy = 0; yy < 32; yy += 8)
        tile[y0 + yy][x] = W[(size_t)(by * 32 + y0 + yy) * C + bx * 32 + x];
    __syncthreads();
#pragma unroll
    for (int yy = 0; yy < 32; yy += 8) {
        float v  = tile[x][y0 + yy];
        float hi = rna_tf32(v);
        size_t o = (size_t)(bx * 32 + y0 + yy) * R + by * 32 + x;
        Dhi[o] = hi;
        Dlo[o] = rna_tf32(v - hi);
    }
}

// Transpose + round Wq [DM][VV] -> Wt [VV][DM] (single tf32)
__global__ void transpose_round_kernel(const float* __restrict__ W) {
    __shared__ float tile[32][33];
    int bx = blockIdx.x;
    int by = blockIdx.y;
    int x  = threadIdx.x;
    int y0 = threadIdx.y;
#pragma unroll
    for (int yy = 0; yy < 32; yy += 8) {
        float v = W[(size_t)(by * 32 + y0 + yy) * VV + bx * 32 + x];
        tile[y0 + yy][x] = rna_tf32(v);
    }
    __syncthreads();
#pragma unroll
    for (int yy = 0; yy < 32; yy += 8)
        g_Wt[(size_t)(bx * 32 + y0 + yy) * DM + by * 32 + x] = tile[x][y0 + yy];
}

// ---------------------------------------------------------------------------
// Shared GEMM geometry
#define KCH    32
#define LSTR   36              // padded smem row stride (floats)
#define TILE_F (128 * LSTR)    // 4608 floats

// ---------------------------------------------------------------------------
// 3xTF32 MLP GEMM (fp32-accurate): C = A @ B^T + bias, A=Ahi+Alo, B=Bhi+Blo
// MODE 0: v=gelu(acc+bias); O1=rna(v), O2=rna(v-O1)   (writes G hi/lo)
// MODE 1: v=acc+bias;       O1=v,      O2=rna(v)      (writes S2, S2r)
#define STG3_F (4 * TILE_F)    // Ahi,Alo,Bhi,Blo per stage
#define SM3_BYTES (2 * STG3_F * 4)   // 147456

template<int MODE>
__global__ void __launch_bounds__(256, 1)
mlp3_kernel(const float* __restrict__ Ahi, const float* __restrict__ Alo,
            const float* __restrict__ Bhi, const float* __restrict__ Blo,
            const float* __restrict__ bias,
            float* __restrict__ O1, float* __restrict__ O2,
            int N, int K)
{
    extern __shared__ float smem[];
    const uint32_t su = smem_u32(smem);
    const int tid     = threadIdx.x;
    const int rowBase = blockIdx.x * 128;
    const int colBase = blockIdx.y * 128;

    const int lane = tid & 31, wid = tid >> 5;
    const int wr = wid >> 1, wc = wid & 1;
    const int g  = lane >> 2, tig = lane & 3;

    float acc[2][8][4];
#pragma unroll
    for (int mt = 0; mt < 2; mt++)
#pragma unroll
        for (int nt = 0; nt < 8; nt++)
#pragma unroll
            for (int k = 0; k < 4; k++) acc[mt][nt][k] = 0.f;

    const float* srcs[4] = {
        Ahi + (size_t)rowBase * K, Alo + (size_t)rowBase * K,
        Bhi + (size_t)colBase * K, Blo + (size_t)colBase * K };

    auto load_stage = [&](int s, int c) {
#pragma unroll
        for (int t = 0; t < 4; t++) {
            uint32_t base = su + (s * STG3_F + t * TILE_F) * 4;
            const float* gp = srcs[t] + c * KCH;
#pragma unroll
            for (int j = 0; j < 4; j++) {
                int idx = tid + 256 * j;         // 0..1023
                int row = idx >> 3, seg = idx & 7;
                cp16(base + (row * LSTR + seg * 4) * 4,
                     gp + (size_t)row * K + seg * 4);
            }
        }
    };

    const int NITER = K / KCH;
    load_stage(0, 0);
    CP_COMMIT();

    for (int it = 0; it < NITER; it++) {
        int s = it & 1;
        CP_WAIT0();
        __syncthreads();
        if (it + 1 < NITER) { load_stage(1 - s, it + 1); CP_COMMIT(); }

        const float* Ah = smem + s * STG3_F;
        const float* Al = Ah + TILE_F;
        const float* Bh = Al + TILE_F;
        const float* Bl = Bh + TILE_F;

#pragma unroll
        for (int k8 = 0; k8 < 4; k8++) {
            int kb = k8 * 8;
            uint32_t ah[2][4], al[2][4];
#pragma unroll
            for (int mt = 0; mt < 2; mt++) {
                int m0 = wr * 32 + mt * 16;
                ah[mt][0] = __float_as_uint(Ah[(m0 + g    ) * LSTR + kb + tig    ]);
                ah[mt][1] = __float_as_uint(Ah[(m0 + g + 8) * LSTR + kb + tig    ]);
                ah[mt][2] = __float_as_uint(Ah[(m0 + g    ) * LSTR + kb + tig + 4]);
                ah[mt][3] = __float_as_uint(Ah[(m0 + g + 8) * LSTR + kb + tig + 4]);
                al[mt][0] = __float_as_uint(Al[(m0 + g    ) * LSTR + kb + tig    ]);
                al[mt][1] = __float_as_uint(Al[(m0 + g + 8) * LSTR + kb + tig    ]);
                al[mt][2] = __float_as_uint(Al[(m0 + g    ) * LSTR + kb + tig + 4]);
                al[mt][3] = __float_as_uint(Al[(m0 + g + 8) * LSTR + kb + tig + 4]);
            }
            uint32_t bh[8][2], bl[8][2];
#pragma unroll
            for (int nt = 0; nt < 8; nt++) {
                int n0 = wc * 64 + nt * 8;
                bh[nt][0] = __float_as_uint(Bh[(n0 + g) * LSTR + kb + tig    ]);
                bh[nt][1] = __float_as_uint(Bh[(n0 + g) * LSTR + kb + tig + 4]);
                bl[nt][0] = __float_as_uint(Bl[(n0 + g) * LSTR + kb + tig    ]);
                bl[nt][1] = __float_as_uint(Bl[(n0 + g) * LSTR + kb + tig + 4]);
            }
#pragma unroll
            for (int mt = 0; mt < 2; mt++)
#pragma unroll
                for (int nt = 0; nt < 8; nt++) {
                    mma_tf32_16x8x8(acc[mt][nt], ah[mt], bh[nt]);
                    mma_tf32_16x8x8(acc[mt][nt], ah[mt], bl[nt]);
                    mma_tf32_16x8x8(acc[mt][nt], al[mt], bh[nt]);
                }
        }
        __syncthreads();
    }

    // Epilogue
#pragma unroll
    for (int mt = 0; mt < 2; mt++) {
        int rb = rowBase + wr * 32 + mt * 16;
        int r0 = rb + g, r1 = rb + g + 8;
#pragma unroll
        for (int nt = 0; nt < 8; nt++) {
            int c = colBase + wc * 64 + nt * 8 + tig * 2;
            float b0 = bias[c], b1v = bias[c + 1];
            float v00 = acc[mt][nt][0] + b0, v01 = acc[mt][nt][1] + b1v;
            float v10 = acc[mt][nt][2] + b0, v11 = acc[mt][nt][3] + b1v;
            if (MODE == 0) {
                v00 = 0.5f * v00 * (1.0f + erff(v00 * 0.70710678118654752f));
                v01 = 0.5f * v01 * (1.0f + erff(v01 * 0.70710678118654752f));
                v10 = 0.5f * v10 * (1.0f + erff(v10 * 0.70710678118654752f));
                v11 = 0.5f * v11 * (1.0f + erff(v11 * 0.70710678118654752f));
                float h00 = rna_tf32(v00), h01 = rna_tf32(v01);
                float h10 = rna_tf32(v10), h11 = rna_tf32(v11);
                *(float2*)&O1[(size_t)r0 * N + c] = make_float2(h00, h01);
                *(float2*)&O1[(size_t)r1 * N + c] = make_float2(h10, h11);
                *(float2*)&O2[(size_t)r0 * N + c] =
                    make_float2(rna_tf32(v00 - h00), rna_tf32(v01 - h01));
                *(float2*)&O2[(size_t)r1 * N + c] =
                    make_float2(rna_tf32(v10 - h10), rna_tf32(v11 - h11));
            } else {
                *(float2*)&O1[(size_t)r0 * N + c] = make_float2(v00, v01);
                *(float2*)&O1[(size_t)r1 * N + c] = make_float2(v10, v11);
                *(float2*)&O2[(size_t)r0 * N + c] =
                    make_float2(rna_tf32(v00), rna_tf32(v01));
                *(float2*)&O2[(size_t)r1 * N + c] =
                    make_float2(rna_tf32(v10), rna_tf32(v11));
            }
        }
    }
}

// ---------------------------------------------------------------------------
// tf32 mma.sync logits GEMM (unchanged from round 3)
#define NITERL (DM / KCH)
#define STG_F  (2 * TILE_F)

__global__ void __launch_bounds__(256, 1)
logits_kernel(const float* __restrict__ Ar, const float* __restrict__ Bt,
              const float* __restrict__ bq, const int* __restrict__ mask,
              float* __restrict__ q)
{
    extern __shared__ float smem[];
    const uint32_t su = smem_u32(smem);
    const int tid     = threadIdx.x;
    const int rowBase = blockIdx.x * 128;
    const int colBase = blockIdx.y * 128;

    const int lane = tid & 31, wid = tid >> 5;
    const int wr = wid >> 1, wc = wid & 1;
    const int g  = lane >> 2, tig = lane & 3;

    float acc[2][8][4];
#pragma unroll
    for (int mt = 0; mt < 2; mt++)
#pragma unroll
        for (int nt = 0; nt < 8; nt++)
#pragma unroll
            for (int k = 0; k < 4; k++) acc[mt][nt][k] = 0.f;

    const float* agbase = Ar + (size_t)rowBase * DM;
    const float* bgbase = Bt + (size_t)colBase * DM;

    auto load_stage = [&](int s, int c) {
        uint32_t abase = su + (s * STG_F) * 4;
        uint32_t bbase = su + (s * STG_F + TILE_F) * 4;
        const float* ag = agbase + c * KCH;
        const float* bg = bgbase + c * KCH;
#pragma unroll
        for (int j = 0; j < 4; j++) {
            int idx = tid + 256 * j;
            int row = idx >> 3, seg = idx & 7;
            cp16(abase + (row * LSTR + seg * 4) * 4, ag + (size_t)row * DM + seg * 4);
        }
#pragma unroll
        for (int j = 0; j < 4; j++) {
            int idx = tid + 256 * j;
            int row = idx >> 3, seg = idx & 7;
            cp16(bbase + (row * LSTR + seg * 4) * 4, bg + (size_t)row * DM + seg * 4);
        }
    };

    load_stage(0, 0);
    CP_COMMIT();

    for (int it = 0; it < NITERL; it++) {
        int s = it & 1;
        CP_WAIT0();
        __syncthreads();
        if (it + 1 < NITERL) { load_stage(1 - s, it + 1); CP_COMMIT(); }

        const float* As = smem + s * STG_F;
        const float* Bs = smem + s * STG_F + TILE_F;

#pragma unroll
        for (int k8 = 0; k8 < 4; k8++) {
            int kb = k8 * 8;
            uint32_t a[2][4];
#pragma unroll
            for (int mt = 0; mt < 2; mt++) {
                int m0 = wr * 32 + mt * 16;
                a[mt][0] = __float_as_uint(As[(m0 + g    ) * LSTR + kb + tig    ]);
                a[mt][1] = __float_as_uint(As[(m0 + g + 8) * LSTR + kb + tig    ]);
                a[mt][2] = __float_as_uint(As[(m0 + g    ) * LSTR + kb + tig + 4]);
                a[mt][3] = __float_as_uint(As[(m0 + g + 8) * LSTR + kb + tig + 4]);
            }
            uint32_t b[8][2];
#pragma unroll
            for (int nt = 0; nt < 8; nt++) {
                int n0 = wc * 64 + nt * 8;
                b[nt][0] = __float_as_uint(Bs[(n0 + g) * LSTR + kb + tig    ]);
                b[nt][1] = __float_as_uint(Bs[(n0 + g) * LSTR + kb + tig + 4]);
            }
#pragma unroll
            for (int mt = 0; mt < 2; mt++)
#pragma unroll
                for (int nt = 0; nt < 8; nt++)
                    mma_tf32_16x8x8(acc[mt][nt], a[mt], b[nt]);
        }
        __syncthreads();
    }

#pragma unroll
    for (int mt = 0; mt < 2; mt++) {
        int rb = rowBase + wr * 32 + mt * 16;
        int r0 = rb + g, r1 = rb + g + 8;
        float m0 = (mask[r0 >> 2] != 0) ? 1.f : 0.f;
        float m1 = (mask[r1 >> 2] != 0) ? 1.f : 0.f;
#pragma unroll
        for (int nt = 0; nt < 8; nt++) {
            int c = colBase + wc * 64 + nt * 8 + tig * 2;
            float bq0 = bq[c], bq1 = bq[c + 1];
            *(float2*)&q[(size_t)r0 * VV + c] =
                make_float2((acc[mt][nt][0] + bq0) * m0, (acc[mt][nt][1] + bq1) * m0);
            *(float2*)&q[(size_t)r1 * VV + c] =
                make_float2((acc[mt][nt][2] + bq0) * m1, (acc[mt][nt][3] + bq1) * m1);
        }
    }
}

// ---------------------------------------------------------------------------
__global__ void beta_kernel(const float* __restrict__ Wb, const float* __restrict__ bbq,
                            const int* __restrict__ mask,
                            float* __restrict__ obeta, float* __restrict__ ok)
{
    int r   = blockIdx.x;
    int tid = threadIdx.x;
    const float* row = g_S2 + (size_t)r * DM;
    float s = 0.f;
    for (int i = tid; i < DM; i += 256) s += row[i] * Wb[i];
    __shared__ float red[256];
    red[tid] = s; __syncthreads();
    for (int o = 128; o > 0; o >>= 1) { if (tid < o) red[tid] += red[tid + o]; __syncthreads(); }
    if (tid == 0) {
        float be = red[0] + bbq[0];
        int   m  = mask[r >> 2];
        float bm = m ? be : 0.f;
        obeta[r]  = bm;
        g_beta[r] = bm;
        float sig = 1.f / (1.f + expf(-bm));
        int k = (int)ceilf(sig * 8.f);
        k = max(1, min(8, k));
        if (sig < 0.25f) k = 0;
        if (!m)          k = 0;
        ok[r] = (float)k;
    }
}

// ---------------------------------------------------------------------------
__global__ void nll_kernel(const float* __restrict__ q, const int* __restrict__ mask,
                           const int* __restrict__ labels)
{
    int r  = blockIdx.x;
    int d  = r & 3;
    int bt = r >> 2;
    int t  = bt % TT;
    int b  = bt / TT;
    int td = t + d + 1;
    bool valid = (td < TT) && (mask[bt] != 0) && (mask[b * TT + td] != 0);
    if (!valid) return;
    int tgt = labels[b * TT + td];

    const float* row = q + (size_t)r * VV;
    int tid = threadIdx.x;
    __shared__ float red[256];

    float mx = -INFINITY;
    for (int i = tid; i < VV; i += 256) mx = fmaxf(mx, row[i]);
    red[tid] = mx; __syncthreads();
    for (int o = 128; o > 0; o >>= 1) { if (tid < o) red[tid] = fmaxf(red[tid], red[tid + o]); __syncthreads(); }
    mx = red[0]; __syncthreads();

    float se = 0.f;
    for (int i = tid; i < VV; i += 256) se += expf(row[i] - mx);
    red[tid] = se; __syncthreads();
    for (int o = 128; o > 0; o >>= 1) { if (tid < o) red[tid] += red[tid + o]; __syncthreads(); }

    if (tid == 0) {
        float nll = logf(red[0]) + mx - row[tgt];
        atomicAdd(&g_acc[0], (double)nll);
        atomicAdd(&g_acc[1], 1.0);
    }
}

// ---------------------------------------------------------------------------
__global__ void bce_kernel(const int* __restrict__ mask)
{
    int idx = blockIdx.x * 256 + threadIdx.x;
    if (idx >= BTN) return;
    int t = idx % TT;
    int b = idx / TT;
    bool m0 = (mask[idx] != 0);
    float bsum = 0.f;
    bool anyv = false;
#pragma unroll
    for (int d = 0; d < 4; d++) {
        int td = t + d + 1;
        bool valid = m0 && (td < TT) && (mask[b * TT + td] != 0);
        float be  = g_beta[idx * 4 + d];
        float bce = fmaxf(be, 0.f) + log1pf(expf(-fabsf(be))) - (valid ? be : 0.f);
        bsum += bce;
        anyv |= valid;
    }
    if (anyv) {
        atomicAdd(&g_acc[2], (double)bsum);
        atomicAdd(&g_acc[3], 1.0);
    }
}

// ---------------------------------------------------------------------------
__global__ void fin_kernel(float* __restrict__ oloss)
{
    double cnt = g_acc[1];
    double Lq  = (cnt > 0.0) ? g_acc[0] / cnt : 0.0;
    double den = g_acc[3]; if (den < 1.0) den = 1.0;
    double Lb  = g_acc[2] / den;
    oloss[0] = (float)(Lq + Lb);
}

// ---------------------------------------------------------------------------
extern "C" void kernel_launch(void* const* d_in, const int* in_sizes, int n_in,
                              void* d_out, int out_size)
{
    const float* H      = (const float*)d_in[0];
    const int*   ids    = (const int*)  d_in[1];
    const int*   mask   = (const int*)  d_in[2];
    const int*   labels = (const int*)  d_in[3];
    const float* emb    = (const float*)d_in[4];
    const float* demb   = (const float*)d_in[5];
    const float* ln_g   = (const float*)d_in[6];
    const float* ln_b   = (const float*)d_in[7];
    const float* W1     = (const float*)d_in[8];
    const float* b1     = (const float*)d_in[9];
    const float* W2     = (const float*)d_in[10];
    const float* b2     = (const float*)d_in[11];
    const float* Wq     = (const float*)d_in[12];
    const float* bq     = (const float*)d_in[13];
    const float* Wb     = (const float*)d_in[14];
    const float* bb     = (const float*)d_in[15];

    float* out   = (float*)d_out;
    float* q     = out;
    float* obeta = out + (size_t)ROWS * VV;
    float* ok    = obeta + ROWS;
    float* oloss = ok + ROWS;

    void *pShi, *pSlo, *pGhi, *pGlo, *pW1h, *pW1l, *pW2h, *pW2l, *pS2, *pS2r, *pWt;
    cudaGetSymbolAddress(&pShi, g_Shi);
    cudaGetSymbolAddress(&pSlo, g_Slo);
    cudaGetSymbolAddress(&pGhi, g_Ghi);
    cudaGetSymbolAddress(&pGlo, g_Glo);
    cudaGetSymbolAddress(&pW1h, g_W1thi);
    cudaGetSymbolAddress(&pW1l, g_W1tlo);
    cudaGetSymbolAddress(&pW2h, g_W2thi);
    cudaGetSymbolAddress(&pW2l, g_W2tlo);
    cudaGetSymbolAddress(&pS2,  g_S2);
    cudaGetSymbolAddress(&pS2r, g_S2r);
    cudaGetSymbolAddress(&pWt,  g_Wt);

    const int smemL = 2 * STG_F * 4;
    cudaFuncSetAttribute(logits_kernel,
                         cudaFuncAttributeMaxDynamicSharedMemorySize, smemL);
    cudaFuncSetAttribute(mlp3_kernel<0>,
                         cudaFuncAttributeMaxDynamicSharedMemorySize, SM3_BYTES);
    cudaFuncSetAttribute(mlp3_kernel<1>,
                         cudaFuncAttributeMaxDynamicSharedMemorySize, SM3_BYTES);

    zero_acc_kernel<<<1, 32>>>();

    // Weight prep
    transpose_round_kernel<<<dim3(VV / 32, DM / 32), dim3(32, 8)>>>(Wq);
    transpose_split_kernel<<<dim3(DH / 32, DM / 32), dim3(32, 8)>>>(
        W1, (float*)pW1h, (float*)pW1l, DM, DH);
    transpose_split_kernel<<<dim3(DM / 32, DH / 32), dim3(32, 8)>>>(
        W2, (float*)pW2h, (float*)pW2l, DH, DM);

    s_kernel<<<ROWS, 256>>>(H, ids, emb, demb, ln_g, ln_b);

    // G(hi/lo) = gelu(S @ W1 + b1)  via 3xTF32
    mlp3_kernel<0><<<dim3(ROWS / 128, DH / 128), 256, SM3_BYTES>>>(
        (const float*)pShi, (const float*)pSlo,
        (const float*)pW1h, (const float*)pW1l,
        b1, (float*)pGhi, (float*)pGlo, DH, DM);

    // S2 / S2r = G @ W2 + b2  via 3xTF32
    mlp3_kernel<1><<<dim3(ROWS / 128, DM / 128), 256, SM3_BYTES>>>(
        (const float*)pGhi, (const float*)pGlo,
        (const float*)pW2h, (const float*)pW2l,
        b2, (float*)pS2, (float*)pS2r, DM, DH);

    // q = mask * (S2r @ Wt^T + bq)
    logits_kernel<<<dim3(ROWS / 128, VV / 128), 256, smemL>>>(
        (const float*)pS2r, (const float*)pWt, bq, mask, q);

    beta_kernel<<<ROWS, 256>>>(Wb, bb, mask, obeta, ok);

    nll_kernel<<<ROWS, 256>>>(q, mask, labels);
    bce_kernel<<<(BTN + 255) / 256, 256>>>(mask);
    fin_kernel<<<1, 1>>>(oloss);

    (void)in_sizes; (void)n_in; (void)out_size;
}

// round 5
// speedup vs baseline: 4.7150x; 1.7692x over previous
#include <cuda_runtime.h>
#include <math.h>
#include <stdint.h>

// Problem constants
#define BB   2
#define TT   512
#define DM   1024
#define DH   4096
#define DD   4
#define VV   32000
#define ROWS (BB*TT*DD)   // 4096
#define BTN  (BB*TT)      // 1024

// Scratch (static device globals — no allocation allowed)
__device__ float  g_Shi [ROWS*DM];
__device__ float  g_Slo [ROWS*DM];
__device__ float  g_Ghi [ROWS*DH];
__device__ float  g_Glo [ROWS*DH];
__device__ float  g_W1thi[DH*DM];
__device__ float  g_W1tlo[DH*DM];
__device__ float  g_W2thi[DM*DH];
__device__ float  g_W2tlo[DM*DH];
__device__ float  g_S2 [ROWS*DM];     // exact fp32 S2 (compacted rows)
__device__ float  g_S2r[ROWS*DM];     // tf32-rounded S2 (compacted rows)
__device__ float  g_Wt [VV*DM];       // transposed+rounded Wq
__device__ float  g_beta[ROWS];       // orig indexing
__device__ int    g_idx [BTN];        // compacted bt index map
__device__ int    g_cnt [1];          // nv4 = 4 * (#valid bt)
__device__ double g_acc[4];

// ============================================================================
__device__ __forceinline__ uint32_t smem_u32(const void* p) {
    uint32_t a;
    asm("{ .reg .u64 t; cvta.to.shared.u64 t, %1; cvt.u32.u64 %0, t; }"
        : "=r"(a) : "l"(p));
    return a;
}
__device__ __forceinline__ float rna_tf32(float v) {
    uint32_t r;
    asm("cvt.rna.tf32.f32 %0, %1;" : "=r"(r) : "f"(v));
    return __uint_as_float(r);
}
__device__ __forceinline__ void cp16(uint32_t s, const void* g) {
    asm volatile("cp.async.cg.shared.global [%0], [%1], 16;" :: "r"(s), "l"(g));
}
#define CP_COMMIT() asm volatile("cp.async.commit_group;" ::: "memory")
#define CP_WAIT0()  asm volatile("cp.async.wait_group 0;" ::: "memory")

__device__ __forceinline__ void mma_tf32_16x8x8(float* d, const uint32_t* a,
                                                const uint32_t* b) {
    asm volatile(
        "mma.sync.aligned.m16n8k8.row.col.f32.tf32.tf32.f32 "
        "{%0,%1,%2,%3}, {%4,%5,%6,%7}, {%8,%9}, {%0,%1,%2,%3};"
        : "+f"(d[0]), "+f"(d[1]), "+f"(d[2]), "+f"(d[3])
        : "r"(a[0]), "r"(a[1]), "r"(a[2]), "r"(a[3]), "r"(b[0]), "r"(b[1]));
}

// ============================================================================
__global__ void zero_acc_kernel() {
    if (threadIdx.x < 4) g_acc[threadIdx.x] = 0.0;
}

// ---------------------------------------------------------------------------
// Compact valid bt positions: g_idx[j] = j-th valid bt, g_cnt = 4*count
__global__ void compact_kernel(const int* __restrict__ mask) {
    __shared__ int pre[BTN];
    int tid = threadIdx.x;                 // 1024 threads
    int m = (mask[tid] != 0) ? 1 : 0;
    pre[tid] = m;
    __syncthreads();
    for (int o = 1; o < BTN; o <<= 1) {
        int v = (tid >= o) ? pre[tid - o] : 0;
        __syncthreads();
        pre[tid] += v;
        __syncthreads();
    }
    int mv = pre[BTN - 1];
    if (m) g_idx[pre[tid] - 1] = tid;
    if (tid >= mv) g_idx[tid] = 0;         // pad (disjoint from valid writes)
    if (tid == 0) g_cnt[0] = mv * 4;
}

// ---------------------------------------------------------------------------
// Zero q / beta / k rows for masked bt positions (one block per bt)
__global__ void zero_fill_kernel(const int* __restrict__ mask,
                                 float* __restrict__ q,
                                 float* __restrict__ obeta,
                                 float* __restrict__ ok)
{
    int bt = blockIdx.x;
    if (mask[bt] != 0) return;
    int tid = threadIdx.x;                 // 256 threads
    float4* dst = (float4*)(q + (size_t)bt * 4 * VV);
#pragma unroll 4
    for (int i = tid; i < 32000; i += 256) dst[i] = make_float4(0.f, 0.f, 0.f, 0.f);
    if (tid < 4) {
        obeta[bt * 4 + tid] = 0.f;
        ok[bt * 4 + tid]    = 0.f;
    }
}

// ---------------------------------------------------------------------------
// S = LayerNorm(H + emb[ids] + depth_emb[d]) * g + b  -> hi/lo (compacted rows)
__global__ void s_kernel(const float* __restrict__ H, const int* __restrict__ ids,
                         const float* __restrict__ emb, const float* __restrict__ demb,
                         const float* __restrict__ lng, const float* __restrict__ lnb)
{
    int rp = blockIdx.x;                   // compacted row
    if (rp >= g_cnt[0]) return;
    int bt  = g_idx[rp >> 2];
    int d   = rp & 3;
    int tid = threadIdx.x;

    const float* hrow = H    + (size_t)bt * DM;
    const float* erow = emb  + (size_t)ids[bt] * DM;
    const float* drow = demb + (size_t)d * DM;

    float x[4];
    float s = 0.f;
#pragma unroll
    for (int j = 0; j < 4; j++) {
        int i = j * 256 + tid;
        x[j] = hrow[i] + erow[i] + drow[i];
        s += x[j];
    }
    __shared__ float red[256];
    red[tid] = s; __syncthreads();
    for (int o = 128; o > 0; o >>= 1) { if (tid < o) red[tid] += red[tid + o]; __syncthreads(); }
    float mu = red[0] * (1.0f / DM);
    __syncthreads();

    float v = 0.f;
#pragma unroll
    for (int j = 0; j < 4; j++) { float dx = x[j] - mu; v += dx * dx; }
    red[tid] = v; __syncthreads();
    for (int o = 128; o > 0; o >>= 1) { if (tid < o) red[tid] += red[tid + o]; __syncthreads(); }
    float inv = rsqrtf(red[0] * (1.0f / DM) + 1e-5f);

#pragma unroll
    for (int j = 0; j < 4; j++) {
        int i = j * 256 + tid;
        float val = (x[j] - mu) * inv * lng[i] + lnb[i];
        float hi  = rna_tf32(val);
        g_Shi[(size_t)rp * DM + i] = hi;
        g_Slo[(size_t)rp * DM + i] = rna_tf32(val - hi);
    }
}

// ---------------------------------------------------------------------------
// Transpose + tf32-split: src[R,C] row-major -> dst_hi/lo[C,R]
__global__ void transpose_split_kernel(const float* __restrict__ W,
                                       float* __restrict__ Dhi, float* __restrict__ Dlo,
                                       int R, int C)
{
    __shared__ float tile[32][33];
    int bx = blockIdx.x;
    int by = blockIdx.y;
    int x  = threadIdx.x;
    int y0 = threadIdx.y;
#pragma unroll
    for (int yy = 0; yy < 32; yy += 8)
        tile[y0 + yy][x] = W[(size_t)(by * 32 + y0 + yy) * C + bx * 32 + x];
    __syncthreads();
#pragma unroll
    for (int yy = 0; yy < 32; yy += 8) {
        float v  = tile[x][y0 + yy];
        float hi = rna_tf32(v);
        size_t o = (size_t)(bx * 32 + y0 + yy) * R + by * 32 + x;
        Dhi[o] = hi;
        Dlo[o] = rna_tf32(v - hi);
    }
}

// Transpose + round Wq [DM][VV] -> Wt [VV][DM]
__global__ void transpose_round_kernel(const float* __restrict__ W) {
    __shared__ float tile[32][33];
    int bx = blockIdx.x;
    int by = blockIdx.y;
    int x  = threadIdx.x;
    int y0 = threadIdx.y;
#pragma unroll
    for (int yy = 0; yy < 32; yy += 8) {
        float v = W[(size_t)(by * 32 + y0 + yy) * VV + bx * 32 + x];
        tile[y0 + yy][x] = rna_tf32(v);
    }
    __syncthreads();
#pragma unroll
    for (int yy = 0; yy < 32; yy += 8)
        g_Wt[(size_t)(bx * 32 + y0 + yy) * DM + by * 32 + x] = tile[x][y0 + yy];
}

// ---------------------------------------------------------------------------
#define KCH    32
#define LSTR   36
#define TILE_F (128 * LSTR)

// 3xTF32 MLP GEMM on compacted rows
#define STG3_F (4 * TILE_F)
#define SM3_BYTES (2 * STG3_F * 4)

template<int MODE>
__global__ void __launch_bounds__(256, 1)
mlp3_kernel(const float* __restrict__ Ahi, const float* __restrict__ Alo,
            const float* __restrict__ Bhi, const float* __restrict__ Blo,
            const float* __restrict__ bias,
            float* __restrict__ O1, float* __restrict__ O2,
            int N, int K)
{
    const int rowBase = blockIdx.x * 128;
    if (rowBase >= g_cnt[0]) return;       // skip fully-invalid tiles
    extern __shared__ float smem[];
    const uint32_t su = smem_u32(smem);
    const int tid     = threadIdx.x;
    const int colBase = blockIdx.y * 128;

    const int lane = tid & 31, wid = tid >> 5;
    const int wr = wid >> 1, wc = wid & 1;
    const int g  = lane >> 2, tig = lane & 3;

    float acc[2][8][4];
#pragma unroll
    for (int mt = 0; mt < 2; mt++)
#pragma unroll
        for (int nt = 0; nt < 8; nt++)
#pragma unroll
            for (int k = 0; k < 4; k++) acc[mt][nt][k] = 0.f;

    const float* srcs[4] = {
        Ahi + (size_t)rowBase * K, Alo + (size_t)rowBase * K,
        Bhi + (size_t)colBase * K, Blo + (size_t)colBase * K };

    auto load_stage = [&](int s, int c) {
#pragma unroll
        for (int t = 0; t < 4; t++) {
            uint32_t base = su + (s * STG3_F + t * TILE_F) * 4;
            const float* gp = srcs[t] + c * KCH;
#pragma unroll
            for (int j = 0; j < 4; j++) {
                int idx = tid + 256 * j;
                int row = idx >> 3, seg = idx & 7;
                cp16(base + (row * LSTR + seg * 4) * 4,
                     gp + (size_t)row * K + seg * 4);
            }
        }
    };

    const int NITER = K / KCH;
    load_stage(0, 0);
    CP_COMMIT();

    for (int it = 0; it < NITER; it++) {
        int s = it & 1;
        CP_WAIT0();
        __syncthreads();
        if (it + 1 < NITER) { load_stage(1 - s, it + 1); CP_COMMIT(); }

        const float* Ah = smem + s * STG3_F;
        const float* Al = Ah + TILE_F;
        const float* Bh = Al + TILE_F;
        const float* Bl = Bh + TILE_F;

#pragma unroll
        for (int k8 = 0; k8 < 4; k8++) {
            int kb = k8 * 8;
            uint32_t ah[2][4], al[2][4];
#pragma unroll
            for (int mt = 0; mt < 2; mt++) {
                int m0 = wr * 32 + mt * 16;
                ah[mt][0] = __float_as_uint(Ah[(m0 + g    ) * LSTR + kb + tig    ]);
                ah[mt][1] = __float_as_uint(Ah[(m0 + g + 8) * LSTR + kb + tig    ]);
                ah[mt][2] = __float_as_uint(Ah[(m0 + g    ) * LSTR + kb + tig + 4]);
                ah[mt][3] = __float_as_uint(Ah[(m0 + g + 8) * LSTR + kb + tig + 4]);
                al[mt][0] = __float_as_uint(Al[(m0 + g    ) * LSTR + kb + tig    ]);
                al[mt][1] = __float_as_uint(Al[(m0 + g + 8) * LSTR + kb + tig    ]);
                al[mt][2] = __float_as_uint(Al[(m0 + g    ) * LSTR + kb + tig + 4]);
                al[mt][3] = __float_as_uint(Al[(m0 + g + 8) * LSTR + kb + tig + 4]);
            }
            uint32_t bh[8][2], bl[8][2];
#pragma unroll
            for (int nt = 0; nt < 8; nt++) {
                int n0 = wc * 64 + nt * 8;
                bh[nt][0] = __float_as_uint(Bh[(n0 + g) * LSTR + kb + tig    ]);
                bh[nt][1] = __float_as_uint(Bh[(n0 + g) * LSTR + kb + tig + 4]);
                bl[nt][0] = __float_as_uint(Bl[(n0 + g) * LSTR + kb + tig    ]);
                bl[nt][1] = __float_as_uint(Bl[(n0 + g) * LSTR + kb + tig + 4]);
            }
#pragma unroll
            for (int mt = 0; mt < 2; mt++)
#pragma unroll
                for (int nt = 0; nt < 8; nt++) {
                    mma_tf32_16x8x8(acc[mt][nt], ah[mt], bh[nt]);
                    mma_tf32_16x8x8(acc[mt][nt], ah[mt], bl[nt]);
                    mma_tf32_16x8x8(acc[mt][nt], al[mt], bh[nt]);
                }
        }
        __syncthreads();
    }

#pragma unroll
    for (int mt = 0; mt < 2; mt++) {
        int rb = rowBase + wr * 32 + mt * 16;
        int r0 = rb + g, r1 = rb + g + 8;
#pragma unroll
        for (int nt = 0; nt < 8; nt++) {
            int c = colBase + wc * 64 + nt * 8 + tig * 2;
            float b0 = bias[c], b1v = bias[c + 1];
            float v00 = acc[mt][nt][0] + b0, v01 = acc[mt][nt][1] + b1v;
            float v10 = acc[mt][nt][2] + b0, v11 = acc[mt][nt][3] + b1v;
            if (MODE == 0) {
                v00 = 0.5f * v00 * (1.0f + erff(v00 * 0.70710678118654752f));
                v01 = 0.5f * v01 * (1.0f + erff(v01 * 0.70710678118654752f));
                v10 = 0.5f * v10 * (1.0f + erff(v10 * 0.70710678118654752f));
                v11 = 0.5f * v11 * (1.0f + erff(v11 * 0.70710678118654752f));
                float h00 = rna_tf32(v00), h01 = rna_tf32(v01);
                float h10 = rna_tf32(v10), h11 = rna_tf32(v11);
                *(float2*)&O1[(size_t)r0 * N + c] = make_float2(h00, h01);
                *(float2*)&O1[(size_t)r1 * N + c] = make_float2(h10, h11);
                *(float2*)&O2[(size_t)r0 * N + c] =
                    make_float2(rna_tf32(v00 - h00), rna_tf32(v01 - h01));
                *(float2*)&O2[(size_t)r1 * N + c] =
                    make_float2(rna_tf32(v10 - h10), rna_tf32(v11 - h11));
            } else {
                *(float2*)&O1[(size_t)r0 * N + c] = make_float2(v00, v01);
                *(float2*)&O1[(size_t)r1 * N + c] = make_float2(v10, v11);
                *(float2*)&O2[(size_t)r0 * N + c] =
                    make_float2(rna_tf32(v00), rna_tf32(v01));
                *(float2*)&O2[(size_t)r1 * N + c] =
                    make_float2(rna_tf32(v10), rna_tf32(v11));
            }
        }
    }
}

// ---------------------------------------------------------------------------
// tf32 logits GEMM on compacted rows; epilogue scatters to original q rows.
#define NITERL (DM / KCH)
#define STG_F  (2 * TILE_F)

__global__ void __launch_bounds__(256, 1)
logits_kernel(const float* __restrict__ Ar, const float* __restrict__ Bt,
              const float* __restrict__ bq, float* __restrict__ q)
{
    const int nv4     = g_cnt[0];
    const int rowBase = blockIdx.x * 128;
    if (rowBase >= nv4) return;
    extern __shared__ float smem[];
    const uint32_t su = smem_u32(smem);
    const int tid     = threadIdx.x;
    const int colBase = blockIdx.y * 128;

    const int lane = tid & 31, wid = tid >> 5;
    const int wr = wid >> 1, wc = wid & 1;
    const int g  = lane >> 2, tig = lane & 3;

    float acc[2][8][4];
#pragma unroll
    for (int mt = 0; mt < 2; mt++)
#pragma unroll
        for (int nt = 0; nt < 8; nt++)
#pragma unroll
            for (int k = 0; k < 4; k++) acc[mt][nt][k] = 0.f;

    const float* agbase = Ar + (size_t)rowBase * DM;
    const float* bgbase = Bt + (size_t)colBase * DM;

    auto load_stage = [&](int s, int c) {
        uint32_t abase = su + (s * STG_F) * 4;
        uint32_t bbase = su + (s * STG_F + TILE_F) * 4;
        const float* ag = agbase + c * KCH;
        const float* bg = bgbase + c * KCH;
#pragma unroll
        for (int j = 0; j < 4; j++) {
            int idx = tid + 256 * j;
            int row = idx >> 3, seg = idx & 7;
            cp16(abase + (row * LSTR + seg * 4) * 4, ag + (size_t)row * DM + seg * 4);
        }
#pragma unroll
        for (int j = 0; j < 4; j++) {
            int idx = tid + 256 * j;
            int row = idx >> 3, seg = idx & 7;
            cp16(bbase + (row * LSTR + seg * 4) * 4, bg + (size_t)row * DM + seg * 4);
        }
    };

    load_stage(0, 0);
    CP_COMMIT();

    for (int it = 0; it < NITERL; it++) {
        int s = it & 1;
        CP_WAIT0();
        __syncthreads();
        if (it + 1 < NITERL) { load_stage(1 - s, it + 1); CP_COMMIT(); }

        const float* As = smem + s * STG_F;
        const float* Bs = smem + s * STG_F + TILE_F;

#pragma unroll
        for (int k8 = 0; k8 < 4; k8++) {
            int kb = k8 * 8;
            uint32_t a[2][4];
#pragma unroll
            for (int mt = 0; mt < 2; mt++) {
                int m0 = wr * 32 + mt * 16;
                a[mt][0] = __float_as_uint(As[(m0 + g    ) * LSTR + kb + tig    ]);
                a[mt][1] = __float_as_uint(As[(m0 + g + 8) * LSTR + kb + tig    ]);
                a[mt][2] = __float_as_uint(As[(m0 + g    ) * LSTR + kb + tig + 4]);
                a[mt][3] = __float_as_uint(As[(m0 + g + 8) * LSTR + kb + tig + 4]);
            }
            uint32_t b[8][2];
#pragma unroll
            for (int nt = 0; nt < 8; nt++) {
                int n0 = wc * 64 + nt * 8;
                b[nt][0] = __float_as_uint(Bs[(n0 + g) * LSTR + kb + tig    ]);
                b[nt][1] = __float_as_uint(Bs[(n0 + g) * LSTR + kb + tig + 4]);
            }
#pragma unroll
            for (int mt = 0; mt < 2; mt++)
#pragma unroll
                for (int nt = 0; nt < 8; nt++)
                    mma_tf32_16x8x8(acc[mt][nt], a[mt], b[nt]);
        }
        __syncthreads();
    }

    // Epilogue: scatter to original rows (valid rows have mask=1)
#pragma unroll
    for (int mt = 0; mt < 2; mt++) {
        int rb  = rowBase + wr * 32 + mt * 16;
        int rc0 = rb + g, rc1 = rb + g + 8;
        int or0 = 0, or1 = 0;
        bool ok0 = rc0 < nv4, ok1 = rc1 < nv4;
        if (ok0) or0 = g_idx[rc0 >> 2] * 4 + (rc0 & 3);
        if (ok1) or1 = g_idx[rc1 >> 2] * 4 + (rc1 & 3);
#pragma unroll
        for (int nt = 0; nt < 8; nt++) {
            int c = colBase + wc * 64 + nt * 8 + tig * 2;
            float bq0 = bq[c], bq1 = bq[c + 1];
            if (ok0)
                *(float2*)&q[(size_t)or0 * VV + c] =
                    make_float2(acc[mt][nt][0] + bq0, acc[mt][nt][1] + bq1);
            if (ok1)
                *(float2*)&q[(size_t)or1 * VV + c] =
                    make_float2(acc[mt][nt][2] + bq0, acc[mt][nt][3] + bq1);
        }
    }
}

// ---------------------------------------------------------------------------
// beta on compacted rows; scatter to orig
__global__ void beta_kernel(const float* __restrict__ Wb, const float* __restrict__ bbq,
                            float* __restrict__ obeta, float* __restrict__ ok)
{
    int rp = blockIdx.x;
    if (rp >= g_cnt[0]) return;
    int tid = threadIdx.x;
    const float* row = g_S2 + (size_t)rp * DM;
    float s = 0.f;
    for (int i = tid; i < DM; i += 256) s += row[i] * Wb[i];
    __shared__ float red[256];
    red[tid] = s; __syncthreads();
    for (int o = 128; o > 0; o >>= 1) { if (tid < o) red[tid] += red[tid + o]; __syncthreads(); }
    if (tid == 0) {
        float be = red[0] + bbq[0];
        int orow = g_idx[rp >> 2] * 4 + (rp & 3);
        obeta[orow]  = be;
        g_beta[orow] = be;
        float sig = 1.f / (1.f + expf(-be));
        int k = (int)ceilf(sig * 8.f);
        k = max(1, min(8, k));
        if (sig < 0.25f) k = 0;
        ok[orow] = (float)k;
    }
}

// ---------------------------------------------------------------------------
__global__ void nll_kernel(const float* __restrict__ q, const int* __restrict__ mask,
                           const int* __restrict__ labels)
{
    int r  = blockIdx.x;
    int d  = r & 3;
    int bt = r >> 2;
    int t  = bt % TT;
    int b  = bt / TT;
    int td = t + d + 1;
    bool valid = (td < TT) && (mask[bt] != 0) && (mask[b * TT + td] != 0);
    if (!valid) return;
    int tgt = labels[b * TT + td];

    const float* row = q + (size_t)r * VV;
    int tid = threadIdx.x;
    __shared__ float red[256];

    float mx = -INFINITY;
    for (int i = tid; i < VV; i += 256) mx = fmaxf(mx, row[i]);
    red[tid] = mx; __syncthreads();
    for (int o = 128; o > 0; o >>= 1) { if (tid < o) red[tid] = fmaxf(red[tid], red[tid + o]); __syncthreads(); }
    mx = red[0]; __syncthreads();

    float se = 0.f;
    for (int i = tid; i < VV; i += 256) se += expf(row[i] - mx);
    red[tid] = se; __syncthreads();
    for (int o = 128; o > 0; o >>= 1) { if (tid < o) red[tid] += red[tid + o]; __syncthreads(); }

    if (tid == 0) {
        float nll = logf(red[0]) + mx - row[tgt];
        atomicAdd(&g_acc[0], (double)nll);
        atomicAdd(&g_acc[1], 1.0);
    }
}

// ---------------------------------------------------------------------------
__global__ void bce_kernel(const int* __restrict__ mask)
{
    int idx = blockIdx.x * 256 + threadIdx.x;
    if (idx >= BTN) return;
    int t = idx % TT;
    int b = idx / TT;
    bool m0 = (mask[idx] != 0);
    if (!m0) return;
    float bsum = 0.f;
    bool anyv = false;
#pragma unroll
    for (int d = 0; d < 4; d++) {
        int td = t + d + 1;
        bool valid = (td < TT) && (mask[b * TT + td] != 0);
        float be  = g_beta[idx * 4 + d];
        float bce = fmaxf(be, 0.f) + log1pf(expf(-fabsf(be))) - (valid ? be : 0.f);
        bsum += bce;
        anyv |= valid;
    }
    if (anyv) {
        atomicAdd(&g_acc[2], (double)bsum);
        atomicAdd(&g_acc[3], 1.0);
    }
}

// ---------------------------------------------------------------------------
__global__ void fin_kernel(float* __restrict__ oloss)
{
    double cnt = g_acc[1];
    double Lq  = (cnt > 0.0) ? g_acc[0] / cnt : 0.0;
    double den = g_acc[3]; if (den < 1.0) den = 1.0;
    double Lb  = g_acc[2] / den;
    oloss[0] = (float)(Lq + Lb);
}

// ---------------------------------------------------------------------------
extern "C" void kernel_launch(void* const* d_in, const int* in_sizes, int n_in,
                              void* d_out, int out_size)
{
    const float* H      = (const float*)d_in[0];
    const int*   ids    = (const int*)  d_in[1];
    const int*   mask   = (const int*)  d_in[2];
    const int*   labels = (const int*)  d_in[3];
    const float* emb    = (const float*)d_in[4];
    const float* demb   = (const float*)d_in[5];
    const float* ln_g   = (const float*)d_in[6];
    const float* ln_b   = (const float*)d_in[7];
    const float* W1     = (const float*)d_in[8];
    const float* b1     = (const float*)d_in[9];
    const float* W2     = (const float*)d_in[10];
    const float* b2     = (const float*)d_in[11];
    const float* Wq     = (const float*)d_in[12];
    const float* bq     = (const float*)d_in[13];
    const float* Wb     = (const float*)d_in[14];
    const float* bb     = (const float*)d_in[15];

    float* out   = (float*)d_out;
    float* q     = out;
    float* obeta = out + (size_t)ROWS * VV;
    float* ok    = obeta + ROWS;
    float* oloss = ok + ROWS;

    void *pShi, *pSlo, *pGhi, *pGlo, *pW1h, *pW1l, *pW2h, *pW2l, *pS2, *pS2r, *pWt;
    cudaGetSymbolAddress(&pShi, g_Shi);
    cudaGetSymbolAddress(&pSlo, g_Slo);
    cudaGetSymbolAddress(&pGhi, g_Ghi);
    cudaGetSymbolAddress(&pGlo, g_Glo);
    cudaGetSymbolAddress(&pW1h, g_W1thi);
    cudaGetSymbolAddress(&pW1l, g_W1tlo);
    cudaGetSymbolAddress(&pW2h, g_W2thi);
    cudaGetSymbolAddress(&pW2l, g_W2tlo);
    cudaGetSymbolAddress(&pS2,  g_S2);
    cudaGetSymbolAddress(&pS2r, g_S2r);
    cudaGetSymbolAddress(&pWt,  g_Wt);

    const int smemL = 2 * STG_F * 4;
    cudaFuncSetAttribute(logits_kernel,
                         cudaFuncAttributeMaxDynamicSharedMemorySize, smemL);
    cudaFuncSetAttribute(mlp3_kernel<0>,
                         cudaFuncAttributeMaxDynamicSharedMemorySize, SM3_BYTES);
    cudaFuncSetAttribute(mlp3_kernel<1>,
                         cudaFuncAttributeMaxDynamicSharedMemorySize, SM3_BYTES);

    zero_acc_kernel<<<1, 32>>>();
    compact_kernel<<<1, BTN>>>(mask);
    zero_fill_kernel<<<BTN, 256>>>(mask, q, obeta, ok);

    // Weight prep
    transpose_round_kernel<<<dim3(VV / 32, DM / 32), dim3(32, 8)>>>(Wq);
    transpose_split_kernel<<<dim3(DH / 32, DM / 32), dim3(32, 8)>>>(
        W1, (float*)pW1h, (float*)pW1l, DM, DH);
    transpose_split_kernel<<<dim3(DM / 32, DH / 32), dim3(32, 8)>>>(
        W2, (float*)pW2h, (float*)pW2l, DH, DM);

    s_kernel<<<ROWS, 256>>>(H, ids, emb, demb, ln_g, ln_b);

    mlp3_kernel<0><<<dim3(ROWS / 128, DH / 128), 256, SM3_BYTES>>>(
        (const float*)pShi, (const float*)pSlo,
        (const float*)pW1h, (const float*)pW1l,
        b1, (float*)pGhi, (float*)pGlo, DH, DM);

    mlp3_kernel<1><<<dim3(ROWS / 128, DM / 128), 256, SM3_BYTES>>>(
        (const float*)pGhi, (const float*)pGlo,
        (const float*)pW2h, (const float*)pW2l,
        b2, (float*)pS2, (float*)pS2r, DM, DH);

    logits_kernel<<<dim3(ROWS / 128, VV / 128), 256, smemL>>>(
        (const float*)pS2r, (const float*)pWt, bq, q);

    beta_kernel<<<ROWS, 256>>>(Wb, bb, obeta, ok);

    nll_kernel<<<ROWS, 256>>>(q, mask, labels);
    bce_kernel<<<(BTN + 255) / 256, 256>>>(mask);
    fin_kernel<<<1, 1>>>(oloss);

    (void)in_sizes; (void)n_in; (void)out_size;
}